// round 11
// baseline (speedup 1.0000x reference)
#include <cuda_runtime.h>
#include <math_constants.h>

// Single-query attention: y = softmax(K @ q) @ V   (fp32, M=131072, D=256)
// Pass1: persistent single-wave (592 = 148 SM x 4 CTAs), 32-row chunks,
// RB=4 two-phase body (K batch -> softmax -> V batch), ~6.7 TB/s (LTS cap).
// Partials stored transposed; (m,l) packed as float2 for one-load access.
// Tail: one flat kernel, 256 blocks; ALL loads front-issued (row loads don't
// depend on gmax), l-sum and column-sum fused into one joint reduction.

#define M_TOTAL   131072
#define DIM       256
#define NCTA      592                      // 148 * 4, one wave
#define NWARPS    8
#define RB        4                        // rows per warp per chunk
#define CHUNK_ROWS (NWARPS * RB)           // 32
#define NCHUNKS   (M_TOTAL / CHUNK_ROWS)   // 4096

// Scratch (allocation-free): ~620 KB
__device__ float  g_partT[DIM][NCTA];      // transposed: [column][cta]
__device__ float2 g_ml[NCTA];              // packed (m, l)

__global__ __launch_bounds__(256, 4)
void sqa_pass1(const float* __restrict__ q,
               const float* __restrict__ K,
               const float* __restrict__ V) {
    const int tid  = threadIdx.x;
    const int warp = tid >> 5;
    const int lane = tid & 31;
    const int bid  = blockIdx.x;

    const float4 q0 = reinterpret_cast<const float4*>(q)[lane];
    const float4 q1 = reinterpret_cast<const float4*>(q)[lane + 32];

    float m = -CUDART_INF_F;
    float l = 0.0f;
    float4 a0 = make_float4(0.f, 0.f, 0.f, 0.f);
    float4 a1 = make_float4(0.f, 0.f, 0.f, 0.f);

    for (int c = bid; c < NCHUNKS; c += NCTA) {
        const int row0 = c * CHUNK_ROWS + warp * RB;

        // -------- K batch: 8 independent LDG.128 --------
        float4 k0[RB], k1[RB];
        #pragma unroll
        for (int j = 0; j < RB; ++j) {
            const float4* Kr =
                reinterpret_cast<const float4*>(K + (size_t)(row0 + j) * DIM);
            k0[j] = Kr[lane];
            k1[j] = Kr[lane + 32];
        }

        float d[RB];
        #pragma unroll
        for (int j = 0; j < RB; ++j) {
            float v = k0[j].x * q0.x + k0[j].y * q0.y + k0[j].z * q0.z + k0[j].w * q0.w
                    + k1[j].x * q1.x + k1[j].y * q1.y + k1[j].z * q1.z + k1[j].w * q1.w;
            #pragma unroll
            for (int off = 16; off > 0; off >>= 1)
                v += __shfl_xor_sync(0xffffffffu, v, off);
            d[j] = v;
        }

        // -------- online softmax update (chunk granularity) --------
        float mc = fmaxf(fmaxf(d[0], d[1]), fmaxf(d[2], d[3]));
        const float mnew  = fmaxf(m, mc);
        const float scale = __expf(m - mnew);   // exp(-inf)=0 on first chunk
        float w[RB];
        #pragma unroll
        for (int j = 0; j < RB; ++j) w[j] = __expf(d[j] - mnew);
        l = l * scale + (w[0] + w[1]) + (w[2] + w[3]);
        m = mnew;

        // -------- V batch: 8 independent LDG.128, weighted accumulate -----
        float4 v0[RB], v1[RB];
        #pragma unroll
        for (int j = 0; j < RB; ++j) {
            const float4* Vr =
                reinterpret_cast<const float4*>(V + (size_t)(row0 + j) * DIM);
            v0[j] = Vr[lane];
            v1[j] = Vr[lane + 32];
        }

        a0.x *= scale; a0.y *= scale; a0.z *= scale; a0.w *= scale;
        a1.x *= scale; a1.y *= scale; a1.z *= scale; a1.w *= scale;
        #pragma unroll
        for (int j = 0; j < RB; ++j) {
            a0.x += w[j] * v0[j].x;  a0.y += w[j] * v0[j].y;
            a0.z += w[j] * v0[j].z;  a0.w += w[j] * v0[j].w;
            a1.x += w[j] * v1[j].x;  a1.y += w[j] * v1[j].y;
            a1.z += w[j] * v1[j].z;  a1.w += w[j] * v1[j].w;
        }
    }

    // ---------------- Merge 8 warps within the CTA ------------------------
    __shared__ float s_m[NWARPS];
    __shared__ float s_l[NWARPS];
    __shared__ float s_acc[NWARPS][DIM];

    if (lane == 0) { s_m[warp] = m; s_l[warp] = l; }
    float* dst = s_acc[warp];
    dst[lane * 4 + 0]       = a0.x;
    dst[lane * 4 + 1]       = a0.y;
    dst[lane * 4 + 2]       = a0.z;
    dst[lane * 4 + 3]       = a0.w;
    dst[128 + lane * 4 + 0] = a1.x;
    dst[128 + lane * 4 + 1] = a1.y;
    dst[128 + lane * 4 + 2] = a1.z;
    dst[128 + lane * 4 + 3] = a1.w;
    __syncthreads();

    float bm = s_m[0];
    #pragma unroll
    for (int w2 = 1; w2 < NWARPS; ++w2) bm = fmaxf(bm, s_m[w2]);

    float y = 0.0f;
    float L = 0.0f;
    #pragma unroll
    for (int w2 = 0; w2 < NWARPS; ++w2) {
        const float sf = __expf(s_m[w2] - bm);
        y += s_acc[w2][tid] * sf;
        L += s_l[w2] * sf;
    }

    // Transposed store: scattered 4B stores (hidden), coalesced tail reads.
    g_partT[tid][bid] = y;
    if (tid == 0) g_ml[bid] = make_float2(bm, L);
}

// Tail: 256 blocks (one per output column) x 256 threads.
// All 9 loads front-issued; one max reduction; one JOINT (l, acc) reduction.
__global__ __launch_bounds__(256)
void sqa_tail(float* __restrict__ out) {
    const int t    = threadIdx.x;
    const int warp = t >> 5;
    const int lane = t & 31;
    const int c    = blockIdx.x;

    __shared__ float s8m[NWARPS];
    __shared__ float s8l[NWARPS];
    __shared__ float s8a[NWARPS];

    const bool has3 = (t < NCTA - 512);

    // ---- front-issue ALL loads (independent; overlap L2 latency) ----
    const float2 ml0 = g_ml[t];
    const float2 ml1 = g_ml[t + 256];
    const float2 ml2 = has3 ? g_ml[t + 512] : make_float2(-CUDART_INF_F, 0.0f);
    const float* row = g_partT[c];
    const float  r0  = row[t];
    const float  r1  = row[t + 256];
    const float  r2  = has3 ? row[t + 512] : 0.0f;

    // ---- round 1: block max ----
    float mv = fmaxf(fmaxf(ml0.x, ml1.x), ml2.x);
    #pragma unroll
    for (int off = 16; off > 0; off >>= 1)
        mv = fmaxf(mv, __shfl_xor_sync(0xffffffffu, mv, off));
    if (lane == 0) s8m[warp] = mv;
    __syncthreads();
    const float gmax = fmaxf(fmaxf(fmaxf(s8m[0], s8m[1]), fmaxf(s8m[2], s8m[3])),
                             fmaxf(fmaxf(s8m[4], s8m[5]), fmaxf(s8m[6], s8m[7])));

    // ---- scale factors (registers) ----
    const float e0 = __expf(ml0.x - gmax);
    const float e1 = __expf(ml1.x - gmax);
    const float e2 = has3 ? __expf(ml2.x - gmax) : 0.0f;

    // ---- round 2: JOINT (l, acc) reduction ----
    float ll  = ml0.y * e0 + ml1.y * e1 + ml2.y * e2;
    float acc = r0 * e0 + r1 * e1 + r2 * e2;
    #pragma unroll
    for (int off = 16; off > 0; off >>= 1) {
        ll  += __shfl_xor_sync(0xffffffffu, ll,  off);
        acc += __shfl_xor_sync(0xffffffffu, acc, off);
    }
    if (lane == 0) { s8l[warp] = ll; s8a[warp] = acc; }
    __syncthreads();
    if (t == 0) {
        const float L = ((s8l[0] + s8l[1]) + (s8l[2] + s8l[3]))
                      + ((s8l[4] + s8l[5]) + (s8l[6] + s8l[7]));
        const float A = ((s8a[0] + s8a[1]) + (s8a[2] + s8a[3]))
                      + ((s8a[4] + s8a[5]) + (s8a[6] + s8a[7]));
        out[c] = A / L;
    }
}

extern "C" void kernel_launch(void* const* d_in, const int* in_sizes, int n_in,
                              void* d_out, int out_size) {
    const float* q = (const float*)d_in[0];
    const float* K = (const float*)d_in[1];
    const float* V = (const float*)d_in[2];
    float* out = (float*)d_out;

    sqa_pass1<<<NCTA, 256>>>(q, K, V);
    sqa_tail<<<DIM, 256>>>(out);
}